// round 4
// baseline (speedup 1.0000x reference)
#include <cuda_runtime.h>
#include <cuda_bf16.h>
#include <cstdint>
#include <cstddef>

// ---------------------------------------------------------------------------
// Problem constants
// ---------------------------------------------------------------------------
#define BB      8
#define LL      1024
#define DM      512
#define DI      1024
#define NSTATE  16
#define RK      32
#define NT      (BB*LL)          // 8192 tokens
#define DEPTH   4

// ---------------------------------------------------------------------------
// Scratch buffers
// ---------------------------------------------------------------------------
__device__ float g_resid[NT*DM];
__device__ float g_h    [NT*DM];
__device__ float g_xz   [NT*2*DI];
__device__ float g_xc   [2*NT*DI];
__device__ float g_xdbl [2*NT*64];
__device__ float g_y    [2*NT*DI];
__device__ float g_o    [2*NT*DM];

// ---------------------------------------------------------------------------
// Helpers
// ---------------------------------------------------------------------------
__device__ __forceinline__ uint32_t smem_u32(const void* p){
    uint32_t a;
    asm("{ .reg .u64 t; cvta.to.shared.u64 t, %1; cvt.u32.u64 %0, t; }" : "=r"(a) : "l"(p));
    return a;
}
__device__ __forceinline__ float warpReduceSum(float v){
#pragma unroll
    for (int o=16;o>0;o>>=1) v += __shfl_xor_sync(0xffffffffu, v, o);
    return v;
}
__device__ __forceinline__ float silu_fast(float x){
    return x / (1.f + __expf(-x));
}

__device__ __forceinline__ void ldm_x4(uint32_t* r, uint32_t addr){
    asm volatile("ldmatrix.sync.aligned.m8n8.x4.shared.b16 {%0,%1,%2,%3}, [%4];"
        : "=r"(r[0]), "=r"(r[1]), "=r"(r[2]), "=r"(r[3]) : "r"(addr));
}
__device__ __forceinline__ void mma_bf16(float* c, const uint32_t* a, const uint32_t* b){
    asm volatile(
        "mma.sync.aligned.m16n8k16.row.col.f32.bf16.bf16.f32 "
        "{%0,%1,%2,%3}, {%4,%5,%6,%7}, {%8,%9}, {%0,%1,%2,%3};"
        : "+f"(c[0]), "+f"(c[1]), "+f"(c[2]), "+f"(c[3])
        : "r"(a[0]), "r"(a[1]), "r"(a[2]), "r"(a[3]), "r"(b[0]), "r"(b[1]));
}

// fp32x4 -> (hi,lo) bf16x4, stored into 80B-pitch smem rows
__device__ __forceinline__ void cvt_store80(char* hi_base, char* lo_base,
                                            int r, int q, float4 v){
    __nv_bfloat162 h0 = __floats2bfloat162_rn(v.x, v.y);
    __nv_bfloat162 h1 = __floats2bfloat162_rn(v.z, v.w);
    float2 f0 = __bfloat1622float2(h0);
    float2 f1 = __bfloat1622float2(h1);
    __nv_bfloat162 l0 = __floats2bfloat162_rn(v.x - f0.x, v.y - f0.y);
    __nv_bfloat162 l1 = __floats2bfloat162_rn(v.z - f1.x, v.w - f1.y);
    const int off = r*80 + q*8;
    uint2 hw, lw;
    hw.x = *reinterpret_cast<uint32_t*>(&h0); hw.y = *reinterpret_cast<uint32_t*>(&h1);
    lw.x = *reinterpret_cast<uint32_t*>(&l0); lw.y = *reinterpret_cast<uint32_t*>(&l1);
    *reinterpret_cast<uint2*>(hi_base + off) = hw;
    *reinterpret_cast<uint2*>(lo_base + off) = lw;
}

// ---------------------------------------------------------------------------
// LayerNorm + residual update, with fused bidirectional add of the previous
// layer's out_proj results (o == nullptr for layer 0).
//   resid_new = src0 + (o ? o_fwd[tok] + o_bwd[flip(tok)] : 0)
//   hout = LN(resid_new)*w + b
// ---------------------------------------------------------------------------
__global__ void __launch_bounds__(128) ln_kernel(
    const float* __restrict__ src0, const float* __restrict__ o,
    float* __restrict__ resid,
    const float* __restrict__ w, const float* __restrict__ b,
    float* __restrict__ hout)
{
    __shared__ float sm[8];
    const int row = blockIdx.x, tid = threadIdx.x;
    float4 v = reinterpret_cast<const float4*>(src0 + (size_t)row*DM)[tid];
    if (o){
        const int t    = row & (LL-1);
        const int tokb = (row - t) + (LL-1 - t);
        float4 u1 = reinterpret_cast<const float4*>(o + (size_t)row*DM)[tid];
        float4 u2 = reinterpret_cast<const float4*>(o + (size_t)(NT + tokb)*DM)[tid];
        v.x += u1.x+u2.x; v.y += u1.y+u2.y; v.z += u1.z+u2.z; v.w += u1.w+u2.w;
    }
    reinterpret_cast<float4*>(resid + (size_t)row*DM)[tid] = v;

    float s = v.x+v.y+v.z+v.w;
    s = warpReduceSum(s);
    const int wid = tid>>5, lane = tid&31;
    if (lane==0) sm[wid]=s;
    __syncthreads();
    const float mu = (sm[0]+sm[1]+sm[2]+sm[3]) * (1.f/(float)DM);
    const float dx=v.x-mu, dy=v.y-mu, dz=v.z-mu, dw=v.w-mu;
    float q = dx*dx+dy*dy+dz*dz+dw*dw;
    q = warpReduceSum(q);
    if (lane==0) sm[4+wid]=q;
    __syncthreads();
    const float var = (sm[4]+sm[5]+sm[6]+sm[7]) * (1.f/(float)DM);
    const float rs = rsqrtf(var + 1e-5f);
    const float4 wv = reinterpret_cast<const float4*>(w)[tid];
    const float4 bv = reinterpret_cast<const float4*>(b)[tid];
    float4 ov;
    ov.x = dx*rs*wv.x + bv.x;
    ov.y = dy*rs*wv.y + bv.y;
    ov.z = dz*rs*wv.z + bv.z;
    ov.w = dw*rs*wv.w + bv.w;
    reinterpret_cast<float4*>(hout + (size_t)row*DM)[tid] = ov;
}

// ---------------------------------------------------------------------------
// Split-bf16 MMA GEMM, double-buffered with register prefetch.
// C[M,N] = A[M,K] * W[N,K]^T  (fp32 in/out; 3-term hi/lo bf16 decomposition)
// BM=128, BK=32, 256 threads. Row pitch 80B => conflict-free ldmatrix.
// Dynamic smem: 2 stages x (A hi/lo + B hi/lo).
// ---------------------------------------------------------------------------
template<int BN>
__global__ void __launch_bounds__(256) gemm_mma_kernel(
    const float* __restrict__ A, int lda,
    const float* __restrict__ W, int K,
    float* __restrict__ C, int ldc)
{
    constexpr int WGN = (BN==128) ? 4 : 2;
    constexpr int WGM = 8/WGN;
    constexpr int WM  = 128/WGM;        // 64 or 32
    constexpr int WN  = BN/WGN;         // 32
    constexpr int MT  = WM/16;          // 4 or 2
    constexpr int NTL = WN/8;           // 4
    constexpr int AHI = 0;
    constexpr int ALO = 128*80;
    constexpr int BHI = 2*128*80;
    constexpr int BLO = BHI + BN*80;
    constexpr int STAGE = BHI + 2*BN*80;

    extern __shared__ char smem[];
    const uint32_t sb = smem_u32(smem);

    const int tid  = threadIdx.x;
    const int wid  = tid>>5, lane = tid&31;
    const int m0   = blockIdx.y*128, n0 = blockIdx.x*BN;
    const int wm0  = (wid/WGN)*WM;
    const int wn0  = (wid%WGN)*WN;

    float acc[MT][NTL][4];
#pragma unroll
    for (int i=0;i<MT;i++)
#pragma unroll
        for (int j=0;j<NTL;j++)
#pragma unroll
            for (int q=0;q<4;q++) acc[i][j][q]=0.f;

    const int a_row = (lane&7) + ((lane>>3)&1)*8;
    const int a_kb  = (lane>>4)*16;
    const int b_row = (lane&7) + (lane>>4)*8;
    const int b_kb  = ((lane>>3)&1)*16;

    // register prefetch of chunk 0
    float4 pa[4];
    float4 pb[BN/32];
#pragma unroll
    for (int u=0;u<4;u++){
        const int flat = tid + u*256;
        const int r = flat>>3, q = flat&7;
        pa[u] = *reinterpret_cast<const float4*>(A + (size_t)(m0+r)*lda + q*4);
    }
#pragma unroll
    for (int u=0;u<BN/32;u++){
        const int flat = tid + u*256;
        const int r = flat>>3, q = flat&7;
        pb[u] = *reinterpret_cast<const float4*>(W + (size_t)(n0+r)*K + q*4);
    }

    const int nchunk = K >> 5;
    for (int c=0; c<nchunk; ++c){
        char* st = smem + (c&1)*STAGE;
        const uint32_t sbs = sb + (uint32_t)((c&1)*STAGE);
        // store prefetched chunk c into smem (cvt fp32 -> hi/lo bf16)
#pragma unroll
        for (int u=0;u<4;u++){
            const int flat = tid + u*256;
            const int r = flat>>3, q = flat&7;
            cvt_store80(st + AHI, st + ALO, r, q, pa[u]);
        }
#pragma unroll
        for (int u=0;u<BN/32;u++){
            const int flat = tid + u*256;
            const int r = flat>>3, q = flat&7;
            cvt_store80(st + BHI, st + BLO, r, q, pb[u]);
        }
        __syncthreads();
        // prefetch chunk c+1 while MMAs consume chunk c
        if (c+1 < nchunk){
            const int k0 = (c+1)*32;
#pragma unroll
            for (int u=0;u<4;u++){
                const int flat = tid + u*256;
                const int r = flat>>3, q = flat&7;
                pa[u] = *reinterpret_cast<const float4*>(A + (size_t)(m0+r)*lda + k0 + q*4);
            }
#pragma unroll
            for (int u=0;u<BN/32;u++){
                const int flat = tid + u*256;
                const int r = flat>>3, q = flat&7;
                pb[u] = *reinterpret_cast<const float4*>(W + (size_t)(n0+r)*K + k0 + q*4);
            }
        }
#pragma unroll
        for (int ks=0; ks<2; ++ks){
            uint32_t ah[MT][4], al[MT][4];
#pragma unroll
            for (int mt=0; mt<MT; ++mt){
                const uint32_t ra = (uint32_t)((wm0 + mt*16 + a_row)*80 + ks*32 + a_kb);
                ldm_x4(ah[mt], sbs + AHI + ra);
                ldm_x4(al[mt], sbs + ALO + ra);
            }
            uint32_t bh[NTL][2], bl[NTL][2];
#pragma unroll
            for (int tp=0; tp<NTL/2; ++tp){
                const uint32_t rb = (uint32_t)((wn0 + tp*16 + b_row)*80 + ks*32 + b_kb);
                uint32_t t4[4];
                ldm_x4(t4, sbs + BHI + rb);
                bh[tp*2][0]=t4[0]; bh[tp*2][1]=t4[1]; bh[tp*2+1][0]=t4[2]; bh[tp*2+1][1]=t4[3];
                ldm_x4(t4, sbs + BLO + rb);
                bl[tp*2][0]=t4[0]; bl[tp*2][1]=t4[1]; bl[tp*2+1][0]=t4[2]; bl[tp*2+1][1]=t4[3];
            }
#pragma unroll
            for (int mt=0; mt<MT; ++mt)
#pragma unroll
                for (int nt=0; nt<NTL; ++nt){
                    mma_bf16(acc[mt][nt], ah[mt], bh[nt]);
                    mma_bf16(acc[mt][nt], ah[mt], bl[nt]);
                    mma_bf16(acc[mt][nt], al[mt], bh[nt]);
                }
        }
    }

    // Epilogue: direct float2 stores from the mma C-fragment layout
    const int cr = lane>>2;
    const int cc = (lane&3)*2;
#pragma unroll
    for (int mt=0; mt<MT; ++mt){
        const int rbase = m0 + wm0 + mt*16 + cr;
#pragma unroll
        for (int nt=0; nt<NTL; ++nt){
            const int col = n0 + wn0 + nt*8 + cc;
            float2 v0; v0.x = acc[mt][nt][0]; v0.y = acc[mt][nt][1];
            float2 v1; v1.x = acc[mt][nt][2]; v1.y = acc[mt][nt][3];
            *reinterpret_cast<float2*>(C + (size_t)rbase*ldc + col)     = v0;
            *reinterpret_cast<float2*>(C + (size_t)(rbase+8)*ldc + col) = v1;
        }
    }
}

// ---------------------------------------------------------------------------
// Depthwise causal conv (k=4) + bias + silu, both directions.
// ---------------------------------------------------------------------------
__global__ void __launch_bounds__(256) conv_kernel(
    const float* __restrict__ xz,
    const float* __restrict__ cw, const float* __restrict__ cb,
    float* __restrict__ xc)
{
    const int flat = blockIdx.x*256 + threadIdx.x;
    const int d   = flat & (DI-1);
    const int t   = (flat >> 10) & (LL-1);
    const int b   = (flat >> 20) & (BB-1);
    const int dir = flat >> 23;

    float acc = cb[d];
    const float w0=cw[d*4+0], w1=cw[d*4+1], w2=cw[d*4+2], w3=cw[d*4+3];
    const float* src = xz + ((size_t)b*LL)*(2*DI) + d;
#pragma unroll
    for (int j=0;j<4;j++){
        const int tt = t - 3 + j;
        if (tt >= 0){
            const int st = dir ? (LL-1-tt) : tt;
            const float wj = (j==0)?w0:(j==1)?w1:(j==2)?w2:w3;
            acc += wj * src[(size_t)st*(2*DI)];
        }
    }
    acc = silu_fast(acc);
    xc[(size_t)dir*NT*DI + ((size_t)(b*LL+t))*DI + d] = acc;
}

// ---------------------------------------------------------------------------
// Selective scan with FUSED dt projection (GEMM3) + D skip + silu(z) gating.
// dt[t][d] = softplus( xdbl[t][0:32] . dtw[d][:] + dtb[d] ) computed inline.
// Fast power-chain path when A rows are multiples of A[...,0].
// ---------------------------------------------------------------------------
#define TTILE 16
__global__ void __launch_bounds__(128) scan_kernel(
    const float* __restrict__ xc,   const float* __restrict__ xdbl,
    const float* __restrict__ xz,
    const float* __restrict__ A_log,const float* __restrict__ Dp,
    const float* __restrict__ dtw,  const float* __restrict__ dtb,
    float* __restrict__ yout)
{
    __shared__ float su [TTILE][128];
    __shared__ float sz [TTILE][128];
    __shared__ float sXD[TTILE][64];

    const int bx  = blockIdx.x;
    const int dir = bx >> 6;
    const int b   = (bx >> 3) & 7;
    const int dch = bx & 7;
    const int tid = threadIdx.x;
    const int d   = dch*128 + tid;

    float a[NSTATE], h[NSTATE];
    bool fast = true;
#pragma unroll
    for (int n=0;n<NSTATE;n++){
        a[n] = -expf(A_log[(size_t)d*NSTATE + n]);
        h[n] = 0.f;
    }
#pragma unroll
    for (int n=1;n<NSTATE;n++){
        fast = fast && (fabsf(a[n] - a[0]*(float)(n+1)) <= 1e-4f*fabsf(a[n]));
    }
    const float a0 = a[0];
    const float Dv = Dp[d];

    float w[RK];
#pragma unroll
    for (int r=0;r<RK;r++) w[r] = dtw[(size_t)d*RK + r];
    const float bias = dtb[d];

    const size_t cb = (size_t)dir*NT*DI + (size_t)(b*LL)*DI + d;
    const float* xcp = xc + cb;
    float*       yp  = yout + cb;
    const float* xdp = xdbl + ((size_t)dir*NT + (size_t)b*LL)*64;
    const float* zp  = xz + (size_t)(b*LL)*(2*DI) + DI + d;

    const int xrow = tid >> 4, xcq = tid & 15;   // 8 rows x 16 float4-cols per pass

    for (int t0=0; t0<LL; t0+=TTILE){
        __syncthreads();
#pragma unroll
        for (int i=0;i<TTILE;i++){
            const int t = t0 + i;
            su [i][tid] = xcp[(size_t)t*DI];
            const int zt = dir ? (LL-1-t) : t;
            sz [i][tid] = zp[(size_t)zt*(2*DI)];
        }
#pragma unroll
        for (int j=0;j<2;j++){
            const int row = xrow + j*8;
            float4 v = *reinterpret_cast<const float4*>(xdp + (size_t)(t0+row)*64 + xcq*4);
            sXD[row][xcq*4+0]=v.x; sXD[row][xcq*4+1]=v.y;
            sXD[row][xcq*4+2]=v.z; sXD[row][xcq*4+3]=v.w;
        }
        __syncthreads();
        if (fast){
#pragma unroll
            for (int i=0;i<TTILE;i++){
                float dtv = bias;
#pragma unroll
                for (int r=0;r<RK;r++) dtv += sXD[i][r]*w[r];
                dtv = (dtv > 20.f) ? dtv : log1pf(__expf(dtv));
                const float u   = su [i][tid];
                const float dtu = dtv * u;
                const float rr  = __expf(dtv * a0);
                float p = 1.f;
                float y = u * Dv;
#pragma unroll
                for (int n=0;n<NSTATE;n++){
                    p *= rr;
                    h[n] = p*h[n] + dtu * sXD[i][32+n];
                    y   += h[n] * sXD[i][48+n];
                }
                y *= silu_fast(sz[i][tid]);
                yp[(size_t)(t0+i)*DI] = y;
            }
        } else {
#pragma unroll
            for (int i=0;i<TTILE;i++){
                float dtv = bias;
#pragma unroll
                for (int r=0;r<RK;r++) dtv += sXD[i][r]*w[r];
                dtv = (dtv > 20.f) ? dtv : log1pf(__expf(dtv));
                const float u   = su [i][tid];
                const float dtu = dtv * u;
                float y = u * Dv;
#pragma unroll
                for (int n=0;n<NSTATE;n++){
                    const float dA = __expf(dtv * a[n]);
                    h[n] = dA*h[n] + dtu * sXD[i][32+n];
                    y   += h[n] * sXD[i][48+n];
                }
                y *= silu_fast(sz[i][tid]);
                yp[(size_t)(t0+i)*DI] = y;
            }
        }
    }
}

// ---------------------------------------------------------------------------
// Final output: hidden[b,t,:] = o_fwd[b,t,:] + o_bwd[b,L-1-t,:]
// ---------------------------------------------------------------------------
__global__ void __launch_bounds__(256) add_kernel(
    const float* __restrict__ o, float* __restrict__ dst)
{
    const int flat = blockIdx.x*256 + threadIdx.x;
    const int e = flat & (DM-1);
    const int t = (flat >> 9) & (LL-1);
    const int b = flat >> 19;
    const int tok  = b*LL + t;
    const int tokb = b*LL + (LL-1-t);
    dst[flat] = o[(size_t)tok*DM + e] + o[(size_t)(NT + tokb)*DM + e];
}

// ---------------------------------------------------------------------------
// Launch
// ---------------------------------------------------------------------------
extern "C" void kernel_launch(void* const* d_in, const int* in_sizes, int n_in,
                              void* d_out, int out_size)
{
    (void)in_sizes; (void)n_in; (void)out_size;
    const float* x      = (const float*)d_in[0];
    const float* norm_w = (const float*)d_in[1];
    const float* norm_b = (const float*)d_in[2];
    const float* in_w   = (const float*)d_in[3];
    const float* conv_w = (const float*)d_in[4];
    const float* conv_b = (const float*)d_in[5];
    const float* xp_w   = (const float*)d_in[6];
    const float* dtp_w  = (const float*)d_in[7];
    const float* dtp_b  = (const float*)d_in[8];
    const float* A_log  = (const float*)d_in[9];
    const float* Dp     = (const float*)d_in[10];
    const float* out_w  = (const float*)d_in[11];
    float* dout = (float*)d_out;

    float *resid,*hbuf,*xz,*xc,*xdbl,*yb,*ob;
    cudaGetSymbolAddress((void**)&resid, g_resid);
    cudaGetSymbolAddress((void**)&hbuf,  g_h);
    cudaGetSymbolAddress((void**)&xz,    g_xz);
    cudaGetSymbolAddress((void**)&xc,    g_xc);
    cudaGetSymbolAddress((void**)&xdbl,  g_xdbl);
    cudaGetSymbolAddress((void**)&yb,    g_y);
    cudaGetSymbolAddress((void**)&ob,    g_o);

    constexpr int SMEM128 = 2*(2*128*80 + 2*128*80);   // 81920
    constexpr int SMEM64  = 2*(2*128*80 + 2*64*80);    // 61440
    static bool attr_done = false;
    if (!attr_done){
        cudaFuncSetAttribute(gemm_mma_kernel<128>,
                             cudaFuncAttributeMaxDynamicSharedMemorySize, SMEM128);
        cudaFuncSetAttribute(gemm_mma_kernel<64>,
                             cudaFuncAttributeMaxDynamicSharedMemorySize, SMEM64);
        attr_done = true;
    }

    for (int i=0;i<DEPTH;i++){
        // residual += (o_fwd + flip(o_bwd)); LN  (fused add for layers > 0)
        ln_kernel<<<NT,128>>>( (i==0)? x : resid, (i==0)? (const float*)nullptr : ob,
                               resid, norm_w + i*DM, norm_b + i*DM, hbuf );

        // GEMM1: xz[8192,2048] = h @ in_w^T
        gemm_mma_kernel<128><<<dim3(2048/128, 8192/128), 256, SMEM128>>>(
            hbuf, DM, in_w + (size_t)i*2*DI*DM, DM, xz, 2*DI);

        conv_kernel<<<(2*NT*DI)/256,256>>>(xz, conv_w + i*DI*4, conv_b + i*DI, xc);

        // GEMM2: xdbl[16384,64] = xc @ xp_w^T
        gemm_mma_kernel<64><<<dim3(1, 16384/128), 256, SMEM64>>>(
            xc, DI, xp_w + (size_t)i*64*DI, DI, xdbl, 64);

        // selective scan with fused dt-projection + gating
        scan_kernel<<<128,128>>>(xc, xdbl, xz,
                                 A_log + (size_t)i*DI*NSTATE, Dp + i*DI,
                                 dtp_w + (size_t)i*DI*RK, dtp_b + i*DI, yb);

        // GEMM4: o[16384,512] = y @ out_w^T
        gemm_mma_kernel<128><<<dim3(512/128, 16384/128), 256, SMEM128>>>(
            yb, DI, out_w + (size_t)i*DM*DI, DI, ob, DM);
    }
    add_kernel<<<(NT*DM)/256,256>>>(ob, dout);
}

// round 5
// speedup vs baseline: 1.0730x; 1.0730x over previous
#include <cuda_runtime.h>
#include <cuda_bf16.h>
#include <cstdint>
#include <cstddef>

// ---------------------------------------------------------------------------
// Problem constants
// ---------------------------------------------------------------------------
#define BB      8
#define LL      1024
#define DM      512
#define DI      1024
#define NSTATE  16
#define RK      32
#define NT      (BB*LL)          // 8192 tokens
#define DEPTH   4

// ---------------------------------------------------------------------------
// Scratch buffers
// ---------------------------------------------------------------------------
__device__ float g_resid[NT*DM];
__device__ float g_h    [NT*DM];
__device__ float g_xz   [NT*2*DI];
__device__ float g_xc   [2*NT*DI];
__device__ float g_xdbl [2*NT*64];
__device__ float g_y    [2*NT*DI];
__device__ float g_o    [2*NT*DM];

// ---------------------------------------------------------------------------
// Helpers
// ---------------------------------------------------------------------------
__device__ __forceinline__ uint32_t smem_u32(const void* p){
    uint32_t a;
    asm("{ .reg .u64 t; cvta.to.shared.u64 t, %1; cvt.u32.u64 %0, t; }" : "=r"(a) : "l"(p));
    return a;
}
__device__ __forceinline__ float warpReduceSum(float v){
#pragma unroll
    for (int o=16;o>0;o>>=1) v += __shfl_xor_sync(0xffffffffu, v, o);
    return v;
}
__device__ __forceinline__ float silu_fast(float x){
    return x / (1.f + __expf(-x));
}

__device__ __forceinline__ void ldm_x4(uint32_t* r, uint32_t addr){
    asm volatile("ldmatrix.sync.aligned.m8n8.x4.shared.b16 {%0,%1,%2,%3}, [%4];"
        : "=r"(r[0]), "=r"(r[1]), "=r"(r[2]), "=r"(r[3]) : "r"(addr));
}
__device__ __forceinline__ void mma_bf16(float* c, const uint32_t* a, const uint32_t* b){
    asm volatile(
        "mma.sync.aligned.m16n8k16.row.col.f32.bf16.bf16.f32 "
        "{%0,%1,%2,%3}, {%4,%5,%6,%7}, {%8,%9}, {%0,%1,%2,%3};"
        : "+f"(c[0]), "+f"(c[1]), "+f"(c[2]), "+f"(c[3])
        : "r"(a[0]), "r"(a[1]), "r"(a[2]), "r"(a[3]), "r"(b[0]), "r"(b[1]));
}

// fp32x4 -> (hi,lo) bf16x4, stored into 80B-pitch smem rows
__device__ __forceinline__ void cvt_store80(char* hi_base, char* lo_base,
                                            int r, int q, float4 v){
    __nv_bfloat162 h0 = __floats2bfloat162_rn(v.x, v.y);
    __nv_bfloat162 h1 = __floats2bfloat162_rn(v.z, v.w);
    float2 f0 = __bfloat1622float2(h0);
    float2 f1 = __bfloat1622float2(h1);
    __nv_bfloat162 l0 = __floats2bfloat162_rn(v.x - f0.x, v.y - f0.y);
    __nv_bfloat162 l1 = __floats2bfloat162_rn(v.z - f1.x, v.w - f1.y);
    const int off = r*80 + q*8;
    uint2 hw, lw;
    hw.x = *reinterpret_cast<uint32_t*>(&h0); hw.y = *reinterpret_cast<uint32_t*>(&h1);
    lw.x = *reinterpret_cast<uint32_t*>(&l0); lw.y = *reinterpret_cast<uint32_t*>(&l1);
    *reinterpret_cast<uint2*>(hi_base + off) = hw;
    *reinterpret_cast<uint2*>(lo_base + off) = lw;
}

// ---------------------------------------------------------------------------
// LayerNorm + residual update, with fused bidirectional add of the previous
// layer's out_proj results (o == nullptr for layer 0).
// ---------------------------------------------------------------------------
__global__ void __launch_bounds__(128) ln_kernel(
    const float* __restrict__ src0, const float* __restrict__ o,
    float* __restrict__ resid,
    const float* __restrict__ w, const float* __restrict__ b,
    float* __restrict__ hout)
{
    __shared__ float sm[8];
    const int row = blockIdx.x, tid = threadIdx.x;
    float4 v = reinterpret_cast<const float4*>(src0 + (size_t)row*DM)[tid];
    if (o){
        const int t    = row & (LL-1);
        const int tokb = (row - t) + (LL-1 - t);
        float4 u1 = reinterpret_cast<const float4*>(o + (size_t)row*DM)[tid];
        float4 u2 = reinterpret_cast<const float4*>(o + (size_t)(NT + tokb)*DM)[tid];
        v.x += u1.x+u2.x; v.y += u1.y+u2.y; v.z += u1.z+u2.z; v.w += u1.w+u2.w;
    }
    reinterpret_cast<float4*>(resid + (size_t)row*DM)[tid] = v;

    float s = v.x+v.y+v.z+v.w;
    s = warpReduceSum(s);
    const int wid = tid>>5, lane = tid&31;
    if (lane==0) sm[wid]=s;
    __syncthreads();
    const float mu = (sm[0]+sm[1]+sm[2]+sm[3]) * (1.f/(float)DM);
    const float dx=v.x-mu, dy=v.y-mu, dz=v.z-mu, dw=v.w-mu;
    float q = dx*dx+dy*dy+dz*dz+dw*dw;
    q = warpReduceSum(q);
    if (lane==0) sm[4+wid]=q;
    __syncthreads();
    const float var = (sm[4]+sm[5]+sm[6]+sm[7]) * (1.f/(float)DM);
    const float rs = rsqrtf(var + 1e-5f);
    const float4 wv = reinterpret_cast<const float4*>(w)[tid];
    const float4 bv = reinterpret_cast<const float4*>(b)[tid];
    float4 ov;
    ov.x = dx*rs*wv.x + bv.x;
    ov.y = dy*rs*wv.y + bv.y;
    ov.z = dz*rs*wv.z + bv.z;
    ov.w = dw*rs*wv.w + bv.w;
    reinterpret_cast<float4*>(hout + (size_t)row*DM)[tid] = ov;
}

// ---------------------------------------------------------------------------
// Split-bf16 MMA GEMM, double-buffered with register prefetch.
// ---------------------------------------------------------------------------
template<int BN>
__global__ void __launch_bounds__(256) gemm_mma_kernel(
    const float* __restrict__ A, int lda,
    const float* __restrict__ W, int K,
    float* __restrict__ C, int ldc)
{
    constexpr int WGN = (BN==128) ? 4 : 2;
    constexpr int WGM = 8/WGN;
    constexpr int WM  = 128/WGM;
    constexpr int WN  = BN/WGN;
    constexpr int MT  = WM/16;
    constexpr int NTL = WN/8;
    constexpr int AHI = 0;
    constexpr int ALO = 128*80;
    constexpr int BHI = 2*128*80;
    constexpr int BLO = BHI + BN*80;
    constexpr int STAGE = BHI + 2*BN*80;

    extern __shared__ char smem[];
    const uint32_t sb = smem_u32(smem);

    const int tid  = threadIdx.x;
    const int wid  = tid>>5, lane = tid&31;
    const int m0   = blockIdx.y*128, n0 = blockIdx.x*BN;
    const int wm0  = (wid/WGN)*WM;
    const int wn0  = (wid%WGN)*WN;

    float acc[MT][NTL][4];
#pragma unroll
    for (int i=0;i<MT;i++)
#pragma unroll
        for (int j=0;j<NTL;j++)
#pragma unroll
            for (int q=0;q<4;q++) acc[i][j][q]=0.f;

    const int a_row = (lane&7) + ((lane>>3)&1)*8;
    const int a_kb  = (lane>>4)*16;
    const int b_row = (lane&7) + (lane>>4)*8;
    const int b_kb  = ((lane>>3)&1)*16;

    float4 pa[4];
    float4 pb[BN/32];
#pragma unroll
    for (int u=0;u<4;u++){
        const int flat = tid + u*256;
        const int r = flat>>3, q = flat&7;
        pa[u] = *reinterpret_cast<const float4*>(A + (size_t)(m0+r)*lda + q*4);
    }
#pragma unroll
    for (int u=0;u<BN/32;u++){
        const int flat = tid + u*256;
        const int r = flat>>3, q = flat&7;
        pb[u] = *reinterpret_cast<const float4*>(W + (size_t)(n0+r)*K + q*4);
    }

    const int nchunk = K >> 5;
    for (int c=0; c<nchunk; ++c){
        char* st = smem + (c&1)*STAGE;
        const uint32_t sbs = sb + (uint32_t)((c&1)*STAGE);
#pragma unroll
        for (int u=0;u<4;u++){
            const int flat = tid + u*256;
            const int r = flat>>3, q = flat&7;
            cvt_store80(st + AHI, st + ALO, r, q, pa[u]);
        }
#pragma unroll
        for (int u=0;u<BN/32;u++){
            const int flat = tid + u*256;
            const int r = flat>>3, q = flat&7;
            cvt_store80(st + BHI, st + BLO, r, q, pb[u]);
        }
        __syncthreads();
        if (c+1 < nchunk){
            const int k0 = (c+1)*32;
#pragma unroll
            for (int u=0;u<4;u++){
                const int flat = tid + u*256;
                const int r = flat>>3, q = flat&7;
                pa[u] = *reinterpret_cast<const float4*>(A + (size_t)(m0+r)*lda + k0 + q*4);
            }
#pragma unroll
            for (int u=0;u<BN/32;u++){
                const int flat = tid + u*256;
                const int r = flat>>3, q = flat&7;
                pb[u] = *reinterpret_cast<const float4*>(W + (size_t)(n0+r)*K + k0 + q*4);
            }
        }
#pragma unroll
        for (int ks=0; ks<2; ++ks){
            uint32_t ah[MT][4], al[MT][4];
#pragma unroll
            for (int mt=0; mt<MT; ++mt){
                const uint32_t ra = (uint32_t)((wm0 + mt*16 + a_row)*80 + ks*32 + a_kb);
                ldm_x4(ah[mt], sbs + AHI + ra);
                ldm_x4(al[mt], sbs + ALO + ra);
            }
            uint32_t bh[NTL][2], bl[NTL][2];
#pragma unroll
            for (int tp=0; tp<NTL/2; ++tp){
                const uint32_t rb = (uint32_t)((wn0 + tp*16 + b_row)*80 + ks*32 + b_kb);
                uint32_t t4[4];
                ldm_x4(t4, sbs + BHI + rb);
                bh[tp*2][0]=t4[0]; bh[tp*2][1]=t4[1]; bh[tp*2+1][0]=t4[2]; bh[tp*2+1][1]=t4[3];
                ldm_x4(t4, sbs + BLO + rb);
                bl[tp*2][0]=t4[0]; bl[tp*2][1]=t4[1]; bl[tp*2+1][0]=t4[2]; bl[tp*2+1][1]=t4[3];
            }
#pragma unroll
            for (int mt=0; mt<MT; ++mt)
#pragma unroll
                for (int nt=0; nt<NTL; ++nt){
                    mma_bf16(acc[mt][nt], ah[mt], bh[nt]);
                    mma_bf16(acc[mt][nt], ah[mt], bl[nt]);
                    mma_bf16(acc[mt][nt], al[mt], bh[nt]);
                }
        }
    }

    const int cr = lane>>2;
    const int cc = (lane&3)*2;
#pragma unroll
    for (int mt=0; mt<MT; ++mt){
        const int rbase = m0 + wm0 + mt*16 + cr;
#pragma unroll
        for (int nt=0; nt<NTL; ++nt){
            const int col = n0 + wn0 + nt*8 + cc;
            float2 v0; v0.x = acc[mt][nt][0]; v0.y = acc[mt][nt][1];
            float2 v1; v1.x = acc[mt][nt][2]; v1.y = acc[mt][nt][3];
            *reinterpret_cast<float2*>(C + (size_t)rbase*ldc + col)     = v0;
            *reinterpret_cast<float2*>(C + (size_t)(rbase+8)*ldc + col) = v1;
        }
    }
}

// ---------------------------------------------------------------------------
// Depthwise causal conv (k=4) + bias + silu, both directions.
// ---------------------------------------------------------------------------
__global__ void __launch_bounds__(256) conv_kernel(
    const float* __restrict__ xz,
    const float* __restrict__ cw, const float* __restrict__ cb,
    float* __restrict__ xc)
{
    const int flat = blockIdx.x*256 + threadIdx.x;
    const int d   = flat & (DI-1);
    const int t   = (flat >> 10) & (LL-1);
    const int b   = (flat >> 20) & (BB-1);
    const int dir = flat >> 23;

    float acc = cb[d];
    const float w0=cw[d*4+0], w1=cw[d*4+1], w2=cw[d*4+2], w3=cw[d*4+3];
    const float* src = xz + ((size_t)b*LL)*(2*DI) + d;
#pragma unroll
    for (int j=0;j<4;j++){
        const int tt = t - 3 + j;
        if (tt >= 0){
            const int st = dir ? (LL-1-tt) : tt;
            const float wj = (j==0)?w0:(j==1)?w1:(j==2)?w2:w3;
            acc += wj * src[(size_t)st*(2*DI)];
        }
    }
    acc = silu_fast(acc);
    xc[(size_t)dir*NT*DI + ((size_t)(b*LL+t))*DI + d] = acc;
}

// ---------------------------------------------------------------------------
// Selective scan with fused dt projection, restructured for ILP:
//  - dt for the whole 16-step tile is computed BEFORE the recurrence
//    (4 parallel accumulators per dot; 16 independent dots).
//  - dA powers via a log-depth tree instead of a 16-deep serial chain.
//  - y uses 4 accumulators.
// ---------------------------------------------------------------------------
#define TTILE 16
__global__ void __launch_bounds__(128) scan_kernel(
    const float* __restrict__ xc,   const float* __restrict__ xdbl,
    const float* __restrict__ xz,
    const float* __restrict__ A_log,const float* __restrict__ Dp,
    const float* __restrict__ dtw,  const float* __restrict__ dtb,
    float* __restrict__ yout)
{
    __shared__ float su [TTILE][128];
    __shared__ float sz [TTILE][128];
    __shared__ float sXD[TTILE][64];

    const int bx  = blockIdx.x;
    const int dir = bx >> 6;
    const int b   = (bx >> 3) & 7;
    const int dch = bx & 7;
    const int tid = threadIdx.x;
    const int d   = dch*128 + tid;

    float a[NSTATE], h[NSTATE];
    bool fast = true;
#pragma unroll
    for (int n=0;n<NSTATE;n++){
        a[n] = -expf(A_log[(size_t)d*NSTATE + n]);
        h[n] = 0.f;
    }
#pragma unroll
    for (int n=1;n<NSTATE;n++){
        fast = fast && (fabsf(a[n] - a[0]*(float)(n+1)) <= 1e-4f*fabsf(a[n]));
    }
    const float a0 = a[0];
    const float Dv = Dp[d];

    float w[RK];
#pragma unroll
    for (int r=0;r<RK;r++) w[r] = dtw[(size_t)d*RK + r];
    const float bias = dtb[d];

    const size_t cb = (size_t)dir*NT*DI + (size_t)(b*LL)*DI + d;
    const float* xcp = xc + cb;
    float*       yp  = yout + cb;
    const float* xdp = xdbl + ((size_t)dir*NT + (size_t)b*LL)*64;
    const float* zp  = xz + (size_t)(b*LL)*(2*DI) + DI + d;

    const int xrow = tid >> 4, xcq = tid & 15;

    for (int t0=0; t0<LL; t0+=TTILE){
        __syncthreads();
#pragma unroll
        for (int i=0;i<TTILE;i++){
            const int t = t0 + i;
            su [i][tid] = xcp[(size_t)t*DI];
            const int zt = dir ? (LL-1-t) : t;
            sz [i][tid] = zp[(size_t)zt*(2*DI)];
        }
#pragma unroll
        for (int j=0;j<2;j++){
            const int row = xrow + j*8;
            float4 v = *reinterpret_cast<const float4*>(xdp + (size_t)(t0+row)*64 + xcq*4);
            sXD[row][xcq*4+0]=v.x; sXD[row][xcq*4+1]=v.y;
            sXD[row][xcq*4+2]=v.z; sXD[row][xcq*4+3]=v.w;
        }
        __syncthreads();

        // ---- tile-parallel dt: 16 independent dots, 4 accumulators each ----
        float dtv[TTILE];
#pragma unroll
        for (int i=0;i<TTILE;i++){
            float a0c=0.f, a1c=0.f, a2c=0.f, a3c=0.f;
#pragma unroll
            for (int r=0;r<RK;r+=4){
                a0c += sXD[i][r+0]*w[r+0];
                a1c += sXD[i][r+1]*w[r+1];
                a2c += sXD[i][r+2]*w[r+2];
                a3c += sXD[i][r+3]*w[r+3];
            }
            float v = bias + ((a0c+a1c)+(a2c+a3c));
            dtv[i] = (v > 20.f) ? v : log1pf(__expf(v));
        }

        if (fast){
#pragma unroll
            for (int i=0;i<TTILE;i++){
                const float dt  = dtv[i];
                const float u   = su[i][tid];
                const float dtu = dt * u;
                const float rr  = __expf(dt * a0);
                // log-depth power tree: q[j]=rr^(j+1), base[g]=rr^(4g)
                const float rr2 = rr*rr;
                const float rr3 = rr2*rr;
                const float rr4 = rr2*rr2;
                const float rr8 = rr4*rr4;
                const float rr12= rr8*rr4;
                float q[4]    = {rr, rr2, rr3, rr4};
                float base[4] = {1.f, rr4, rr8, rr12};
                float y0 = u*Dv, y1=0.f, y2=0.f, y3=0.f;
#pragma unroll
                for (int g=0; g<4; ++g){
#pragma unroll
                    for (int j=0; j<4; ++j){
                        const int n = g*4 + j;
                        const float p = base[g]*q[j];
                        h[n] = p*h[n] + dtu * sXD[i][32+n];
                        const float c = h[n] * sXD[i][48+n];
                        if (j==0) y0 += c; else if (j==1) y1 += c;
                        else if (j==2) y2 += c; else y3 += c;
                    }
                }
                float y = (y0+y1)+(y2+y3);
                y *= silu_fast(sz[i][tid]);
                yp[(size_t)(t0+i)*DI] = y;
            }
        } else {
#pragma unroll
            for (int i=0;i<TTILE;i++){
                const float dt  = dtv[i];
                const float u   = su[i][tid];
                const float dtu = dt * u;
                float y = u * Dv;
#pragma unroll
                for (int n=0;n<NSTATE;n++){
                    const float dA = __expf(dt * a[n]);
                    h[n] = dA*h[n] + dtu * sXD[i][32+n];
                    y   += h[n] * sXD[i][48+n];
                }
                y *= silu_fast(sz[i][tid]);
                yp[(size_t)(t0+i)*DI] = y;
            }
        }
    }
}

// ---------------------------------------------------------------------------
// Final output: hidden[b,t,:] = o_fwd[b,t,:] + o_bwd[b,L-1-t,:]
// ---------------------------------------------------------------------------
__global__ void __launch_bounds__(256) add_kernel(
    const float* __restrict__ o, float* __restrict__ dst)
{
    const int flat = blockIdx.x*256 + threadIdx.x;
    const int e = flat & (DM-1);
    const int t = (flat >> 9) & (LL-1);
    const int b = flat >> 19;
    const int tok  = b*LL + t;
    const int tokb = b*LL + (LL-1-t);
    dst[flat] = o[(size_t)tok*DM + e] + o[(size_t)(NT + tokb)*DM + e];
}

// ---------------------------------------------------------------------------
// Launch
// ---------------------------------------------------------------------------
extern "C" void kernel_launch(void* const* d_in, const int* in_sizes, int n_in,
                              void* d_out, int out_size)
{
    (void)in_sizes; (void)n_in; (void)out_size;
    const float* x      = (const float*)d_in[0];
    const float* norm_w = (const float*)d_in[1];
    const float* norm_b = (const float*)d_in[2];
    const float* in_w   = (const float*)d_in[3];
    const float* conv_w = (const float*)d_in[4];
    const float* conv_b = (const float*)d_in[5];
    const float* xp_w   = (const float*)d_in[6];
    const float* dtp_w  = (const float*)d_in[7];
    const float* dtp_b  = (const float*)d_in[8];
    const float* A_log  = (const float*)d_in[9];
    const float* Dp     = (const float*)d_in[10];
    const float* out_w  = (const float*)d_in[11];
    float* dout = (float*)d_out;

    float *resid,*hbuf,*xz,*xc,*xdbl,*yb,*ob;
    cudaGetSymbolAddress((void**)&resid, g_resid);
    cudaGetSymbolAddress((void**)&hbuf,  g_h);
    cudaGetSymbolAddress((void**)&xz,    g_xz);
    cudaGetSymbolAddress((void**)&xc,    g_xc);
    cudaGetSymbolAddress((void**)&xdbl,  g_xdbl);
    cudaGetSymbolAddress((void**)&yb,    g_y);
    cudaGetSymbolAddress((void**)&ob,    g_o);

    constexpr int SMEM128 = 2*(2*128*80 + 2*128*80);   // 81920
    constexpr int SMEM64  = 2*(2*128*80 + 2*64*80);    // 61440
    static bool attr_done = false;
    if (!attr_done){
        cudaFuncSetAttribute(gemm_mma_kernel<128>,
                             cudaFuncAttributeMaxDynamicSharedMemorySize, SMEM128);
        cudaFuncSetAttribute(gemm_mma_kernel<64>,
                             cudaFuncAttributeMaxDynamicSharedMemorySize, SMEM64);
        attr_done = true;
    }

    for (int i=0;i<DEPTH;i++){
        ln_kernel<<<NT,128>>>( (i==0)? x : resid, (i==0)? (const float*)nullptr : ob,
                               resid, norm_w + i*DM, norm_b + i*DM, hbuf );

        gemm_mma_kernel<128><<<dim3(2048/128, 8192/128), 256, SMEM128>>>(
            hbuf, DM, in_w + (size_t)i*2*DI*DM, DM, xz, 2*DI);

        conv_kernel<<<(2*NT*DI)/256,256>>>(xz, conv_w + i*DI*4, conv_b + i*DI, xc);

        gemm_mma_kernel<64><<<dim3(1, 16384/128), 256, SMEM64>>>(
            xc, DI, xp_w + (size_t)i*64*DI, DI, xdbl, 64);

        scan_kernel<<<128,128>>>(xc, xdbl, xz,
                                 A_log + (size_t)i*DI*NSTATE, Dp + i*DI,
                                 dtp_w + (size_t)i*DI*RK, dtp_b + i*DI, yb);

        gemm_mma_kernel<128><<<dim3(512/128, 16384/128), 256, SMEM128>>>(
            yb, DI, out_w + (size_t)i*DM*DI, DI, ob, DM);
    }
    add_kernel<<<(NT*DM)/256,256>>>(ob, dout);
}